// round 6
// baseline (speedup 1.0000x reference)
#include <cuda_runtime.h>
#include <cuda_bf16.h>
#include <cstdint>
#include <cstring>

#define BN 2
#define CIN 64
#define HH 256
#define WW 256
#define KK 9
#define OC1 10
#define HW (HH*WW)

// ---------------- scratch ----------------
__device__ float g_off[BN*OC1*HW];
__device__ float g_offpart[BN*256*20];    // per-conv1-block (sum,sumsq) x 10 ch
__device__ float g_offstats[BN*5*2];
__device__ __align__(16) __nv_bfloat16 g_wbf[2*KK*4096];  // [split][k][swizzled 64co x 64ci]
__device__ float g_part[BN*512*16*2];
__device__ float g_outmr[BN*16*2];

// ---------------- mma helpers (baseline PTX, no 'a' features) ----------------
__device__ __forceinline__ uint32_t smem_u32(const void* p) {
    uint32_t a;
    asm("{ .reg .u64 t; cvta.to.shared.u64 t, %1; cvt.u32.u64 %0, t; }" : "=r"(a) : "l"(p));
    return a;
}
__device__ __forceinline__ void ldsm_x4(uint32_t* r, uint32_t addr) {
    asm volatile("ldmatrix.sync.aligned.m8n8.x4.shared.b16 {%0,%1,%2,%3}, [%4];"
                 : "=r"(r[0]), "=r"(r[1]), "=r"(r[2]), "=r"(r[3]) : "r"(addr));
}
__device__ __forceinline__ void ldsm_x2(uint32_t* r, uint32_t addr) {
    asm volatile("ldmatrix.sync.aligned.m8n8.x2.shared.b16 {%0,%1}, [%2];"
                 : "=r"(r[0]), "=r"(r[1]) : "r"(addr));
}
__device__ __forceinline__ void mma16816(float* d, const uint32_t* a, const uint32_t* b) {
    asm volatile("mma.sync.aligned.m16n8k16.row.col.f32.bf16.bf16.f32 "
                 "{%0,%1,%2,%3}, {%4,%5,%6,%7}, {%8,%9}, {%0,%1,%2,%3};"
                 : "+f"(d[0]), "+f"(d[1]), "+f"(d[2]), "+f"(d[3])
                 : "r"(a[0]), "r"(a[1]), "r"(a[2]), "r"(a[3]), "r"(b[0]), "r"(b[1]));
}
__device__ __forceinline__ void cpasync16(uint32_t saddr, const void* gptr) {
    asm volatile("cp.async.ca.shared.global [%0], [%1], 16;" :: "r"(saddr), "l"(gptr) : "memory");
}

// smem layout (dynamic), single stage
#define OFF_SHI  0           // [128 pix][64 ci] bf16 swizzled (16 KB)
#define OFF_SLO  16384
#define OFF_WHI  32768       // [64 co][64 ci] bf16 swizzled (8 KB)
#define OFF_WLO  40960
#define OFF_IY   49152       // 9*128 floats
#define OFF_SUMS 53760       // 32 floats
#define SMEM_BYTES 53888

// ---------------- kernel 1: 3x3 conv, 64 -> 10 channels (+ GN stat partials) ----------------
__global__ void conv1_kernel(const float* __restrict__ x,
                             const float* __restrict__ w,
                             const float* __restrict__ bias) {
    int b = blockIdx.z, w0 = blockIdx.x * 32, h0 = blockIdx.y * 8;
    int t = threadIdx.x;
    int tw = t & 31, th = t >> 5;
    __shared__ float xs[10][34];
    __shared__ float ws[OC1][9];
    __shared__ float red[8][20];
    float acc[OC1];
#pragma unroll
    for (int o = 0; o < OC1; o++) acc[o] = 0.f;

    for (int ci = 0; ci < CIN; ci++) {
        for (int i = t; i < 340; i += 256) {
            int r = i / 34, c = i % 34;
            int hy = h0 - 1 + r, wx = w0 - 1 + c;
            float v = 0.f;
            if (hy >= 0 && hy < HH && wx >= 0 && wx < WW)
                v = x[((size_t)(b*CIN + ci)*HH + hy)*WW + wx];
            xs[r][c] = v;
        }
        if (t < OC1*9) ws[t/9][t%9] = w[(t/9)*CIN*9 + ci*9 + (t%9)];
        __syncthreads();

        float xv[9];
#pragma unroll
        for (int dy = 0; dy < 3; dy++)
#pragma unroll
            for (int dx = 0; dx < 3; dx++)
                xv[dy*3+dx] = xs[th+dy][tw+dx];
#pragma unroll
        for (int o = 0; o < OC1; o++) {
            float a = acc[o];
#pragma unroll
            for (int tp = 0; tp < 9; tp++) a = fmaf(ws[o][tp], xv[tp], a);
            acc[o] = a;
        }
        __syncthreads();
    }
    int lane = t & 31, wid = t >> 5;
#pragma unroll
    for (int o = 0; o < OC1; o++) {
        float v = acc[o] + bias[o];
        g_off[((size_t)(b*OC1 + o)*HH + h0 + th)*WW + w0 + tw] = v;
        float s = v, q = v*v;
#pragma unroll
        for (int m = 16; m; m >>= 1) {
            s += __shfl_xor_sync(0xffffffff, s, m);
            q += __shfl_xor_sync(0xffffffff, q, m);
        }
        if (lane == 0) { red[wid][o*2] = s; red[wid][o*2+1] = q; }
    }
    __syncthreads();
    if (t < 20) {
        float a = 0.f;
#pragma unroll
        for (int wq = 0; wq < 8; wq++) a += red[wq][t];
        int blk = blockIdx.x + 8*blockIdx.y;   // 0..255
        g_offpart[((size_t)(b*256) + blk)*20 + t] = a;
    }
}

// ---------------- kernel 2: reduce offset GN partials ----------------
__global__ void offstats_kernel() {
    int b = blockIdx.x / 5, g = blockIdx.x % 5;
    int t = threadIdx.x;
    float s = 0.f, q = 0.f;
    for (int i = t; i < 256; i += 256) {
        const float* p = g_offpart + ((size_t)(b*256) + i)*20;
        s += p[(2*g)*2]   + p[(2*g+1)*2];
        q += p[(2*g)*2+1] + p[(2*g+1)*2+1];
    }
    __shared__ float rs[256], rq[256];
    rs[t] = s; rq[t] = q; __syncthreads();
    for (int o = 128; o > 0; o >>= 1) {
        if (t < o) { rs[t] += rs[t+o]; rq[t] += rq[t+o]; }
        __syncthreads();
    }
    if (t == 0) {
        float n = (float)(2*HW);
        float mean = rs[0] / n;
        float var = rq[0] / n - mean*mean;
        g_offstats[(b*5+g)*2]   = mean;
        g_offstats[(b*5+g)*2+1] = rsqrtf(var + 1e-5f);
    }
}

// ---------------- kernel 3: split w_dsc into bf16 hi/lo, [k][co][ci] swizzled ----------------
__global__ void wprep_kernel(const float* __restrict__ wdsc) {
    int lin = blockIdx.x*256 + threadIdx.x;       // 9*64*64
    if (lin >= KK*64*64) return;
    int ci = lin & 63, co = (lin >> 6) & 63, k = lin >> 12;
    float v = wdsc[((size_t)(co*64 + ci))*KK + k];
    __nv_bfloat16 hi = __float2bfloat16(v);
    __nv_bfloat16 lo = __float2bfloat16(v - __bfloat162float(hi));
    uint32_t off = (uint32_t)(co*128 + ci*2);
    uint32_t sw = off ^ ((off >> 3) & 0x70);
    *(__nv_bfloat16*)((char*)g_wbf + (size_t)k*8192 + sw) = hi;
    *(__nv_bfloat16*)((char*)g_wbf + (size_t)(KK + k)*8192 + sw) = lo;
}

// ---------------- kernel 4: fused coords + sampling + mma.sync GEMM ----------------
// CTA: 128 pixels (N) x 64 co (M), K = 9 taps x 64 ci. 256 threads, 4 CTAs/SM.
__global__ void __launch_bounds__(256, 4)
main_kernel(const float* __restrict__ x,
            const float* __restrict__ gno_w, const float* __restrict__ gno_b,
            const float* __restrict__ b_dsc,
            float* __restrict__ out) {
    extern __shared__ __align__(16) char smem[];
    uint32_t sb = smem_u32(smem);
    float* iy_sh = (float*)(smem + OFF_IY);
    float* sums  = (float*)(smem + OFF_SUMS);

    int t = threadIdx.x, lane = t & 31, wid = t >> 5;
    int b = blockIdx.z, h = blockIdx.y, w0 = blockIdx.x * 128;
    if (t < 32) sums[t] = 0.f;

    // Phase 0: GN+tanh, outward cumsum, clamped iy for 128 pixels x 9 taps
    if (t < 128) {
        int p = t, wg = w0 + p;
        float v[9];
#pragma unroll
        for (int c = 0; c < 9; c++) {
            float raw = g_off[((size_t)(b*OC1 + c)*HH + h)*WW + wg];
            int g = c >> 1;
            float mean = g_offstats[(b*5+g)*2];
            float rstd = g_offstats[(b*5+g)*2+1];
            v[c] = tanhf((raw - mean)*rstd*gno_w[c] + gno_b[c]);
        }
        float cum[9];
        cum[4] = 0.f;
        cum[3] = v[3]; cum[2] = cum[3]+v[2]; cum[1] = cum[2]+v[1]; cum[0] = cum[1]+v[0];
        cum[5] = v[5]; cum[6] = cum[5]+v[6]; cum[7] = cum[6]+v[7]; cum[8] = cum[7]+v[8];
#pragma unroll
        for (int k = 0; k < 9; k++)
            iy_sh[k*128 + p] = fminf(fmaxf((float)h + cum[k], 0.f), 255.f);
    }

    const float* xb = x + (size_t)b*CIN*HW;
    int pixw = (wid & 3)*32 + lane;      // sampling: pixel this thread owns
    int ci0base = (wid >> 2)*32;         // sampling: ci chunk base

    // mma warp tiling: wm in {0,1} -> 32 co, wn in {0..3} -> 32 pix
    int wm = wid & 1, wn = wid >> 1;
    float acc[2][4][4];
#pragma unroll
    for (int i = 0; i < 2; i++)
#pragma unroll
        for (int j = 0; j < 4; j++)
#pragma unroll
            for (int l = 0; l < 4; l++) acc[i][j][l] = 0.f;

    for (int k = 0; k < KK; k++) {
        __syncthreads();   // previous mma phase done reading S/W; iy_sh ready (k=0)

        // ---- async copy this tap's weight tiles (pre-swizzled, L2-hot) ----
        {
            const char* whsrc = (const char*)g_wbf + (size_t)k*8192 + t*32;
            const char* wlsrc = (const char*)g_wbf + (size_t)(KK + k)*8192 + t*32;
            cpasync16(sb + OFF_WHI + t*32,      whsrc);
            cpasync16(sb + OFF_WHI + t*32 + 16, whsrc + 16);
            cpasync16(sb + OFF_WLO + t*32,      wlsrc);
            cpasync16(sb + OFF_WLO + t*32 + 16, wlsrc + 16);
            asm volatile("cp.async.commit_group;" ::: "memory");
        }

        // ---- sampling: S[pix][ci] bf16 hi/lo, swizzled 128B rows ----
        float iy = iy_sh[k*128 + pixw];
        float y0f = floorf(iy);
        float wy = iy - y0f;
        int y0 = (int)y0f;
        int y1 = min(y0 + 1, 255);
        int ix = min(max(w0 + pixw + k - 4, 0), 255);
        const float* p0 = xb + y0*WW + ix;
        const float* p1 = xb + y1*WW + ix;

#pragma unroll
        for (int g = 0; g < 4; g++) {
            int ci0 = ci0base + g*8;
            float v[8];
#pragma unroll
            for (int j = 0; j < 8; j++) {
                size_t o = (size_t)(ci0 + j)*HW;
                float a = __ldg(p0 + o), c = __ldg(p1 + o);
                v[j] = fmaf(c - a, wy, a);
            }
            uint32_t hp[4], lp[4];
#pragma unroll
            for (int j = 0; j < 4; j++) {
                __nv_bfloat162 h2 = __floats2bfloat162_rn(v[2*j], v[2*j+1]);
                float2 hf = __bfloat1622float2(h2);
                __nv_bfloat162 l2 = __floats2bfloat162_rn(v[2*j] - hf.x, v[2*j+1] - hf.y);
                memcpy(&hp[j], &h2, 4);
                memcpy(&lp[j], &l2, 4);
            }
            uint32_t off = (uint32_t)(pixw*128 + ci0*2);
            uint32_t sw = off ^ ((off >> 3) & 0x70);
            *(uint4*)(smem + OFF_SHI + sw) = make_uint4(hp[0], hp[1], hp[2], hp[3]);
            *(uint4*)(smem + OFF_SLO + sw) = make_uint4(lp[0], lp[1], lp[2], lp[3]);
        }

        asm volatile("cp.async.wait_group 0;" ::: "memory");
        __syncthreads();

        // ---- mma phase: 4 ksteps of 16 ci (b-frags loaded per-nt to cap regs) ----
#pragma unroll
        for (int kt = 0; kt < 4; kt++) {
            uint32_t ahi[2][4], alo[2][4];
#pragma unroll
            for (int mt = 0; mt < 2; mt++) {
                uint32_t row = (uint32_t)(wm*32 + mt*16 + (lane & 15));
                uint32_t c16 = (uint32_t)(kt*2 + (lane >> 4));
                uint32_t off = row*128 + c16*16;
                uint32_t sw = off ^ ((off >> 3) & 0x70);
                ldsm_x4(ahi[mt], sb + OFF_WHI + sw);
                ldsm_x4(alo[mt], sb + OFF_WLO + sw);
            }
#pragma unroll
            for (int nt = 0; nt < 4; nt++) {
                uint32_t bhi[2], blo[2];
                uint32_t row = (uint32_t)(wn*32 + nt*8 + (lane & 7));
                uint32_t c16 = (uint32_t)(kt*2 + ((lane >> 3) & 1));
                uint32_t off = row*128 + c16*16;
                uint32_t sw = off ^ ((off >> 3) & 0x70);
                ldsm_x2(bhi, sb + OFF_SHI + sw);
                ldsm_x2(blo, sb + OFF_SLO + sw);
#pragma unroll
                for (int mt = 0; mt < 2; mt++) {
                    mma16816(acc[mt][nt], ahi[mt], bhi);
                    mma16816(acc[mt][nt], alo[mt], bhi);
                    mma16816(acc[mt][nt], ahi[mt], blo);
                }
            }
        }
    }

    // ---- epilogue: bias, store, GN partial sums ----
    {
        int q = lane >> 2;                    // co row within tile
        int pp = (lane & 3) * 2;              // pixel pair
        float s_l[2][2] = {{0.f,0.f},{0.f,0.f}}, q_l[2][2] = {{0.f,0.f},{0.f,0.f}};
#pragma unroll
        for (int mt = 0; mt < 2; mt++) {
            int cog = wm*32 + mt*16 + q;
            float b0 = __ldg(b_dsc + cog);
            float b1 = __ldg(b_dsc + cog + 8);
#pragma unroll
            for (int nt = 0; nt < 4; nt++) {
                int pix = wn*32 + nt*8 + pp;
                float v0 = acc[mt][nt][0] + b0;
                float v1 = acc[mt][nt][1] + b0;
                float v2 = acc[mt][nt][2] + b1;
                float v3 = acc[mt][nt][3] + b1;
                *(float2*)&out[((size_t)(b*64 + cog)*HH + h)*WW + w0 + pix]     = make_float2(v0, v1);
                *(float2*)&out[((size_t)(b*64 + cog + 8)*HH + h)*WW + w0 + pix] = make_float2(v2, v3);
                s_l[mt][0] += v0 + v1; q_l[mt][0] += v0*v0 + v1*v1;
                s_l[mt][1] += v2 + v3; q_l[mt][1] += v2*v2 + v3*v3;
            }
        }
#pragma unroll
        for (int mt = 0; mt < 2; mt++)
#pragma unroll
            for (int hf = 0; hf < 2; hf++) {
#pragma unroll
                for (int m = 1; m <= 2; m <<= 1) {
                    s_l[mt][hf] += __shfl_xor_sync(0xffffffff, s_l[mt][hf], m);
                    q_l[mt][hf] += __shfl_xor_sync(0xffffffff, q_l[mt][hf], m);
                }
                if ((lane & 3) == 0) {
                    int grp = (wm*32 + mt*16 + hf*8 + q) >> 2;
                    atomicAdd(&sums[2*grp],   s_l[mt][hf]);
                    atomicAdd(&sums[2*grp+1], q_l[mt][hf]);
                }
            }
    }
    __syncthreads();
    if (t < 32) {
        int bw = blockIdx.x + 2*h;     // 0..511 within batch
        g_part[((size_t)(b*512 + bw)*16 + (t >> 1))*2 + (t & 1)] = sums[t];
    }
}

// ---------------- kernel 5: reduce out-GN partials ----------------
__global__ void outstats_kernel() {
    int b = blockIdx.x >> 4, g = blockIdx.x & 15;
    int t = threadIdx.x;
    float s = 0.f, q = 0.f;
    for (int i = t; i < 512; i += 256) {
        size_t idx = ((size_t)(b*512 + i)*16 + g)*2;
        s += g_part[idx];
        q += g_part[idx + 1];
    }
    __shared__ float rs[256], rq[256];
    rs[t] = s; rq[t] = q; __syncthreads();
    for (int o = 128; o > 0; o >>= 1) {
        if (t < o) { rs[t] += rs[t+o]; rq[t] += rq[t+o]; }
        __syncthreads();
    }
    if (t == 0) {
        float n = 4.f * HW;
        float mean = rs[0] / n;
        float var = rq[0] / n - mean*mean;
        g_outmr[(b*16+g)*2]   = mean;
        g_outmr[(b*16+g)*2+1] = rsqrtf(var + 1e-5f);
    }
}

// ---------------- kernel 6: apply GN + ReLU ----------------
__global__ void apply_kernel(float* __restrict__ out,
                             const float* __restrict__ gn_w,
                             const float* __restrict__ gn_b) {
    int idx4 = blockIdx.x*blockDim.x + threadIdx.x;
    size_t base = (size_t)idx4 * 4;
    int co = (int)((base >> 16) & 63);
    int b  = (int)(base >> 22);
    int g  = co >> 2;
    float mean = g_outmr[(b*16+g)*2];
    float rstd = g_outmr[(b*16+g)*2+1];
    float sc = rstd * gn_w[co];
    float sh = gn_b[co] - mean * sc;
    float4 v = *(float4*)&out[base];
    v.x = fmaxf(fmaf(v.x, sc, sh), 0.f);
    v.y = fmaxf(fmaf(v.y, sc, sh), 0.f);
    v.z = fmaxf(fmaf(v.z, sc, sh), 0.f);
    v.w = fmaxf(fmaf(v.w, sc, sh), 0.f);
    *(float4*)&out[base] = v;
}

// ---------------- launch ----------------
extern "C" void kernel_launch(void* const* d_in, const int* in_sizes, int n_in,
                              void* d_out, int out_size) {
    const float* x     = (const float*)d_in[0];
    const float* w_off = (const float*)d_in[1];
    const float* b_off = (const float*)d_in[2];
    const float* gno_w = (const float*)d_in[3];
    const float* gno_b = (const float*)d_in[4];
    const float* w_dsc = (const float*)d_in[5];
    const float* b_dsc = (const float*)d_in[6];
    const float* gn_w  = (const float*)d_in[7];
    const float* gn_b  = (const float*)d_in[8];
    float* out = (float*)d_out;

    cudaFuncSetAttribute(main_kernel, cudaFuncAttributeMaxDynamicSharedMemorySize, SMEM_BYTES);

    conv1_kernel<<<dim3(WW/32, HH/8, BN), 256>>>(x, w_off, b_off);
    offstats_kernel<<<BN*5, 256>>>();
    wprep_kernel<<<(KK*64*64 + 255)/256, 256>>>(w_dsc);
    main_kernel<<<dim3(2, HH, BN), 256, SMEM_BYTES>>>(x, gno_w, gno_b, b_dsc, out);
    outstats_kernel<<<BN*16, 256>>>();
    apply_kernel<<<4096, 512>>>(out, gn_w, gn_b);
}

// round 7
// speedup vs baseline: 1.0127x; 1.0127x over previous
#include <cuda_runtime.h>
#include <cuda_bf16.h>
#include <cstdint>
#include <cstring>

#define BN 2
#define CIN 64
#define HH 256
#define WW 256
#define KK 9
#define OC1 10
#define HW (HH*WW)

// ---------------- scratch ----------------
__device__ float g_off[BN*OC1*HW];
__device__ float g_offpart[BN*256*20];    // per-conv1-block (sum,sumsq) x 10 ch
__device__ float g_offstats[BN*5*2];
__device__ __align__(16) __nv_bfloat16 g_wbf[2*KK*4096];  // [split][k][swizzled 64co x 64ci]
__device__ float g_part[BN*512*16*2];
__device__ float g_outmr[BN*16*2];

// ---------------- mma helpers (baseline PTX, no 'a' features) ----------------
__device__ __forceinline__ uint32_t smem_u32(const void* p) {
    uint32_t a;
    asm("{ .reg .u64 t; cvta.to.shared.u64 t, %1; cvt.u32.u64 %0, t; }" : "=r"(a) : "l"(p));
    return a;
}
__device__ __forceinline__ void ldsm_x4(uint32_t* r, uint32_t addr) {
    asm volatile("ldmatrix.sync.aligned.m8n8.x4.shared.b16 {%0,%1,%2,%3}, [%4];"
                 : "=r"(r[0]), "=r"(r[1]), "=r"(r[2]), "=r"(r[3]) : "r"(addr));
}
__device__ __forceinline__ void ldsm_x2(uint32_t* r, uint32_t addr) {
    asm volatile("ldmatrix.sync.aligned.m8n8.x2.shared.b16 {%0,%1}, [%2];"
                 : "=r"(r[0]), "=r"(r[1]) : "r"(addr));
}
__device__ __forceinline__ void mma16816(float* d, const uint32_t* a, const uint32_t* b) {
    asm volatile("mma.sync.aligned.m16n8k16.row.col.f32.bf16.bf16.f32 "
                 "{%0,%1,%2,%3}, {%4,%5,%6,%7}, {%8,%9}, {%0,%1,%2,%3};"
                 : "+f"(d[0]), "+f"(d[1]), "+f"(d[2]), "+f"(d[3])
                 : "r"(a[0]), "r"(a[1]), "r"(a[2]), "r"(a[3]), "r"(b[0]), "r"(b[1]));
}
__device__ __forceinline__ void cpasync16(uint32_t saddr, const void* gptr) {
    asm volatile("cp.async.ca.shared.global [%0], [%1], 16;" :: "r"(saddr), "l"(gptr) : "memory");
}

// smem layout (dynamic), single stage
#define OFF_SHI  0           // [128 pix][64 ci] bf16 swizzled (16 KB)
#define OFF_SLO  16384
#define OFF_WHI  32768       // [64 co][64 ci] bf16 swizzled (8 KB)
#define OFF_WLO  40960
#define OFF_IY   49152       // 9*128 floats
#define OFF_SUMS 53760       // 32 floats
#define SMEM_BYTES 53888

// ---------------- kernel 1: 3x3 conv, 64 -> 10 channels (+ GN stat partials) ----------------
__global__ void __launch_bounds__(256)
conv1_kernel(const float* __restrict__ x,
             const float* __restrict__ w,
             const float* __restrict__ bias) {
    int b = blockIdx.z, w0 = blockIdx.x * 32, h0 = blockIdx.y * 8;
    int t = threadIdx.x;
    int tw = t & 31, th = t >> 5;
    __shared__ float xs[2][10][34];
    __shared__ float ws[CIN][OC1*9];      // all weights, [ci][o*9+tap]
    __shared__ float red[8][20];
    float acc[OC1];
#pragma unroll
    for (int o = 0; o < OC1; o++) acc[o] = 0.f;

    // preload all weights (5760 floats)
    for (int i = t; i < CIN*OC1*9; i += 256) {
        int ci = i / (OC1*9), r = i % (OC1*9);
        ws[ci][r] = w[(r/9)*CIN*9 + ci*9 + (r%9)];
    }
    // preload halo tile for ci=0 into buf 0
    {
        for (int i = t; i < 340; i += 256) {
            int r = i / 34, c = i % 34;
            int hy = h0 - 1 + r, wx = w0 - 1 + c;
            float v = 0.f;
            if (hy >= 0 && hy < HH && wx >= 0 && wx < WW)
                v = x[((size_t)(b*CIN + 0)*HH + hy)*WW + wx];
            xs[0][r][c] = v;
        }
    }
    __syncthreads();

    int i0 = t, i1 = t + 256;     // halo element indices this thread loads
    int r0 = i0 / 34, c0 = i0 % 34;
    int r1 = i1 / 34, c1 = i1 % 34;
    int hy0 = h0 - 1 + r0, wx0 = w0 - 1 + c0;
    int hy1 = h0 - 1 + r1, wx1 = w0 - 1 + c1;
    bool in0 = (i0 < 340) && hy0 >= 0 && hy0 < HH && wx0 >= 0 && wx0 < WW;
    bool in1 = (i1 < 340) && hy1 >= 0 && hy1 < HH && wx1 >= 0 && wx1 < WW;

    for (int ci = 0; ci < CIN; ci++) {
        int buf = ci & 1;
        // issue loads for ci+1 (into regs; stored after compute)
        float l0 = 0.f, l1 = 0.f;
        if (ci + 1 < CIN) {
            const float* xp = x + ((size_t)(b*CIN + ci + 1)*HH)*WW;
            if (in0) l0 = __ldg(xp + (size_t)hy0*WW + wx0);
            if (in1) l1 = __ldg(xp + (size_t)hy1*WW + wx1);
        }

        // compute from xs[buf]
        float xv[9];
#pragma unroll
        for (int dy = 0; dy < 3; dy++)
#pragma unroll
            for (int dx = 0; dx < 3; dx++)
                xv[dy*3+dx] = xs[buf][th+dy][tw+dx];
        const float* wr = ws[ci];
#pragma unroll
        for (int o = 0; o < OC1; o++) {
            float a = acc[o];
#pragma unroll
            for (int tp = 0; tp < 9; tp++) a = fmaf(wr[o*9+tp], xv[tp], a);
            acc[o] = a;
        }

        // store next tile
        if (ci + 1 < CIN) {
            if (i0 < 340) xs[buf^1][r0][c0] = l0;
            if (i1 < 340) xs[buf^1][r1][c1] = l1;
        }
        __syncthreads();
    }

    int lane = t & 31, wid = t >> 5;
#pragma unroll
    for (int o = 0; o < OC1; o++) {
        float v = acc[o] + bias[o];
        g_off[((size_t)(b*OC1 + o)*HH + h0 + th)*WW + w0 + tw] = v;
        float s = v, q = v*v;
#pragma unroll
        for (int m = 16; m; m >>= 1) {
            s += __shfl_xor_sync(0xffffffff, s, m);
            q += __shfl_xor_sync(0xffffffff, q, m);
        }
        if (lane == 0) { red[wid][o*2] = s; red[wid][o*2+1] = q; }
    }
    __syncthreads();
    if (t < 20) {
        float a = 0.f;
#pragma unroll
        for (int wq = 0; wq < 8; wq++) a += red[wq][t];
        int blk = blockIdx.x + 8*blockIdx.y;   // 0..255
        g_offpart[((size_t)(b*256) + blk)*20 + t] = a;
    }
}

// ---------------- kernel 2: reduce offset GN partials ----------------
__global__ void offstats_kernel() {
    int b = blockIdx.x / 5, g = blockIdx.x % 5;
    int t = threadIdx.x;
    float s = 0.f, q = 0.f;
    for (int i = t; i < 256; i += 256) {
        const float* p = g_offpart + ((size_t)(b*256) + i)*20;
        s += p[(2*g)*2]   + p[(2*g+1)*2];
        q += p[(2*g)*2+1] + p[(2*g+1)*2+1];
    }
    __shared__ float rs[256], rq[256];
    rs[t] = s; rq[t] = q; __syncthreads();
    for (int o = 128; o > 0; o >>= 1) {
        if (t < o) { rs[t] += rs[t+o]; rq[t] += rq[t+o]; }
        __syncthreads();
    }
    if (t == 0) {
        float n = (float)(2*HW);
        float mean = rs[0] / n;
        float var = rq[0] / n - mean*mean;
        g_offstats[(b*5+g)*2]   = mean;
        g_offstats[(b*5+g)*2+1] = rsqrtf(var + 1e-5f);
    }
}

// ---------------- kernel 3: split w_dsc into bf16 hi/lo, [k][co][ci] swizzled ----------------
__global__ void wprep_kernel(const float* __restrict__ wdsc) {
    int lin = blockIdx.x*256 + threadIdx.x;       // 9*64*64
    if (lin >= KK*64*64) return;
    int ci = lin & 63, co = (lin >> 6) & 63, k = lin >> 12;
    float v = wdsc[((size_t)(co*64 + ci))*KK + k];
    __nv_bfloat16 hi = __float2bfloat16(v);
    __nv_bfloat16 lo = __float2bfloat16(v - __bfloat162float(hi));
    uint32_t off = (uint32_t)(co*128 + ci*2);
    uint32_t sw = off ^ ((off >> 3) & 0x70);
    *(__nv_bfloat16*)((char*)g_wbf + (size_t)k*8192 + sw) = hi;
    *(__nv_bfloat16*)((char*)g_wbf + (size_t)(KK + k)*8192 + sw) = lo;
}

// ---------------- kernel 4: fused coords + sampling + mma.sync GEMM ----------------
// CTA: 128 pixels (N) x 64 co (M), K = 9 taps x 64 ci. 256 threads, 3 CTAs/SM.
__global__ void __launch_bounds__(256, 3)
main_kernel(const float* __restrict__ x,
            const float* __restrict__ gno_w, const float* __restrict__ gno_b,
            const float* __restrict__ b_dsc,
            float* __restrict__ out) {
    extern __shared__ __align__(16) char smem[];
    uint32_t sb = smem_u32(smem);
    float* iy_sh = (float*)(smem + OFF_IY);
    float* sums  = (float*)(smem + OFF_SUMS);

    int t = threadIdx.x, lane = t & 31, wid = t >> 5;
    int b = blockIdx.z, h = blockIdx.y, w0 = blockIdx.x * 128;
    if (t < 32) sums[t] = 0.f;

    // Phase 0: GN+tanh, outward cumsum, clamped iy for 128 pixels x 9 taps
    if (t < 128) {
        int p = t, wg = w0 + p;
        float v[9];
#pragma unroll
        for (int c = 0; c < 9; c++) {
            float raw = g_off[((size_t)(b*OC1 + c)*HH + h)*WW + wg];
            int g = c >> 1;
            float mean = g_offstats[(b*5+g)*2];
            float rstd = g_offstats[(b*5+g)*2+1];
            v[c] = tanhf((raw - mean)*rstd*gno_w[c] + gno_b[c]);
        }
        float cum[9];
        cum[4] = 0.f;
        cum[3] = v[3]; cum[2] = cum[3]+v[2]; cum[1] = cum[2]+v[1]; cum[0] = cum[1]+v[0];
        cum[5] = v[5]; cum[6] = cum[5]+v[6]; cum[7] = cum[6]+v[7]; cum[8] = cum[7]+v[8];
#pragma unroll
        for (int k = 0; k < 9; k++)
            iy_sh[k*128 + p] = fminf(fmaxf((float)h + cum[k], 0.f), 255.f);
    }

    const float* xb = x + (size_t)b*CIN*HW;
    int pixw = (wid & 3)*32 + lane;      // sampling: pixel this thread owns
    int ci0base = (wid >> 2)*32;         // sampling: ci chunk base

    // mma warp tiling: wm in {0,1} -> 32 co, wn in {0..3} -> 32 pix
    int wm = wid & 1, wn = wid >> 1;
    float acc[2][4][4];
#pragma unroll
    for (int i = 0; i < 2; i++)
#pragma unroll
        for (int j = 0; j < 4; j++)
#pragma unroll
            for (int l = 0; l < 4; l++) acc[i][j][l] = 0.f;

    for (int k = 0; k < KK; k++) {
        __syncthreads();   // previous mma phase done reading S/W; iy_sh ready (k=0)

        // ---- async copy this tap's weight tiles (pre-swizzled, L2-hot) ----
        {
            const char* whsrc = (const char*)g_wbf + (size_t)k*8192 + t*32;
            const char* wlsrc = (const char*)g_wbf + (size_t)(KK + k)*8192 + t*32;
            cpasync16(sb + OFF_WHI + t*32,      whsrc);
            cpasync16(sb + OFF_WHI + t*32 + 16, whsrc + 16);
            cpasync16(sb + OFF_WLO + t*32,      wlsrc);
            cpasync16(sb + OFF_WLO + t*32 + 16, wlsrc + 16);
            asm volatile("cp.async.commit_group;" ::: "memory");
        }

        // ---- sampling: S[pix][ci] bf16 hi/lo, swizzled 128B rows ----
        float iy = iy_sh[k*128 + pixw];
        float y0f = floorf(iy);
        float wy = iy - y0f;
        int y0 = (int)y0f;
        int y1 = min(y0 + 1, 255);
        int ix = min(max(w0 + pixw + k - 4, 0), 255);
        const float* p0 = xb + y0*WW + ix;
        const float* p1 = xb + y1*WW + ix;

#pragma unroll
        for (int g = 0; g < 4; g++) {
            int ci0 = ci0base + g*8;
            float v[8];
#pragma unroll
            for (int j = 0; j < 8; j++) {
                size_t o = (size_t)(ci0 + j)*HW;
                float a = __ldg(p0 + o), c = __ldg(p1 + o);
                v[j] = fmaf(c - a, wy, a);
            }
            uint32_t hp[4], lp[4];
#pragma unroll
            for (int j = 0; j < 4; j++) {
                __nv_bfloat162 h2 = __floats2bfloat162_rn(v[2*j], v[2*j+1]);
                float2 hf = __bfloat1622float2(h2);
                __nv_bfloat162 l2 = __floats2bfloat162_rn(v[2*j] - hf.x, v[2*j+1] - hf.y);
                memcpy(&hp[j], &h2, 4);
                memcpy(&lp[j], &l2, 4);
            }
            uint32_t off = (uint32_t)(pixw*128 + ci0*2);
            uint32_t sw = off ^ ((off >> 3) & 0x70);
            *(uint4*)(smem + OFF_SHI + sw) = make_uint4(hp[0], hp[1], hp[2], hp[3]);
            *(uint4*)(smem + OFF_SLO + sw) = make_uint4(lp[0], lp[1], lp[2], lp[3]);
        }

        asm volatile("cp.async.wait_group 0;" ::: "memory");
        __syncthreads();

        // ---- mma phase: 4 ksteps of 16 ci ----
#pragma unroll
        for (int kt = 0; kt < 4; kt++) {
            uint32_t ahi[2][4], alo[2][4];
#pragma unroll
            for (int mt = 0; mt < 2; mt++) {
                uint32_t row = (uint32_t)(wm*32 + mt*16 + (lane & 15));
                uint32_t c16 = (uint32_t)(kt*2 + (lane >> 4));
                uint32_t off = row*128 + c16*16;
                uint32_t sw = off ^ ((off >> 3) & 0x70);
                ldsm_x4(ahi[mt], sb + OFF_WHI + sw);
                ldsm_x4(alo[mt], sb + OFF_WLO + sw);
            }
            uint32_t bhi[4][2], blo[4][2];
#pragma unroll
            for (int nt = 0; nt < 4; nt++) {
                uint32_t row = (uint32_t)(wn*32 + nt*8 + (lane & 7));
                uint32_t c16 = (uint32_t)(kt*2 + ((lane >> 3) & 1));
                uint32_t off = row*128 + c16*16;
                uint32_t sw = off ^ ((off >> 3) & 0x70);
                ldsm_x2(bhi[nt], sb + OFF_SHI + sw);
                ldsm_x2(blo[nt], sb + OFF_SLO + sw);
            }
#pragma unroll
            for (int mt = 0; mt < 2; mt++)
#pragma unroll
                for (int nt = 0; nt < 4; nt++) {
                    mma16816(acc[mt][nt], ahi[mt], bhi[nt]);
                    mma16816(acc[mt][nt], alo[mt], bhi[nt]);
                    mma16816(acc[mt][nt], ahi[mt], blo[nt]);
                }
        }
    }

    // ---- epilogue: bias, store, GN partial sums ----
    {
        int q = lane >> 2;                    // co row within tile
        int pp = (lane & 3) * 2;              // pixel pair
        float s_l[2][2] = {{0.f,0.f},{0.f,0.f}}, q_l[2][2] = {{0.f,0.f},{0.f,0.f}};
#pragma unroll
        for (int mt = 0; mt < 2; mt++) {
            int cog = wm*32 + mt*16 + q;
            float b0 = __ldg(b_dsc + cog);
            float b1 = __ldg(b_dsc + cog + 8);
#pragma unroll
            for (int nt = 0; nt < 4; nt++) {
                int pix = wn*32 + nt*8 + pp;
                float v0 = acc[mt][nt][0] + b0;
                float v1 = acc[mt][nt][1] + b0;
                float v2 = acc[mt][nt][2] + b1;
                float v3 = acc[mt][nt][3] + b1;
                *(float2*)&out[((size_t)(b*64 + cog)*HH + h)*WW + w0 + pix]     = make_float2(v0, v1);
                *(float2*)&out[((size_t)(b*64 + cog + 8)*HH + h)*WW + w0 + pix] = make_float2(v2, v3);
                s_l[mt][0] += v0 + v1; q_l[mt][0] += v0*v0 + v1*v1;
                s_l[mt][1] += v2 + v3; q_l[mt][1] += v2*v2 + v3*v3;
            }
        }
#pragma unroll
        for (int mt = 0; mt < 2; mt++)
#pragma unroll
            for (int hf = 0; hf < 2; hf++) {
#pragma unroll
                for (int m = 1; m <= 2; m <<= 1) {
                    s_l[mt][hf] += __shfl_xor_sync(0xffffffff, s_l[mt][hf], m);
                    q_l[mt][hf] += __shfl_xor_sync(0xffffffff, q_l[mt][hf], m);
                }
                if ((lane & 3) == 0) {
                    int grp = (wm*32 + mt*16 + hf*8 + q) >> 2;
                    atomicAdd(&sums[2*grp],   s_l[mt][hf]);
                    atomicAdd(&sums[2*grp+1], q_l[mt][hf]);
                }
            }
    }
    __syncthreads();
    if (t < 32) {
        int bw = blockIdx.x + 2*h;     // 0..511 within batch
        g_part[((size_t)(b*512 + bw)*16 + (t >> 1))*2 + (t & 1)] = sums[t];
    }
}

// ---------------- kernel 5: reduce out-GN partials ----------------
__global__ void outstats_kernel() {
    int b = blockIdx.x >> 4, g = blockIdx.x & 15;
    int t = threadIdx.x;
    float s = 0.f, q = 0.f;
    for (int i = t; i < 512; i += 256) {
        size_t idx = ((size_t)(b*512 + i)*16 + g)*2;
        s += g_part[idx];
        q += g_part[idx + 1];
    }
    __shared__ float rs[256], rq[256];
    rs[t] = s; rq[t] = q; __syncthreads();
    for (int o = 128; o > 0; o >>= 1) {
        if (t < o) { rs[t] += rs[t+o]; rq[t] += rq[t+o]; }
        __syncthreads();
    }
    if (t == 0) {
        float n = 4.f * HW;
        float mean = rs[0] / n;
        float var = rq[0] / n - mean*mean;
        g_outmr[(b*16+g)*2]   = mean;
        g_outmr[(b*16+g)*2+1] = rsqrtf(var + 1e-5f);
    }
}

// ---------------- kernel 6: apply GN + ReLU ----------------
__global__ void apply_kernel(float* __restrict__ out,
                             const float* __restrict__ gn_w,
                             const float* __restrict__ gn_b) {
    int idx4 = blockIdx.x*blockDim.x + threadIdx.x;
    size_t base = (size_t)idx4 * 4;
    int co = (int)((base >> 16) & 63);
    int b  = (int)(base >> 22);
    int g  = co >> 2;
    float mean = g_outmr[(b*16+g)*2];
    float rstd = g_outmr[(b*16+g)*2+1];
    float sc = rstd * gn_w[co];
    float sh = gn_b[co] - mean * sc;
    float4 v = *(float4*)&out[base];
    v.x = fmaxf(fmaf(v.x, sc, sh), 0.f);
    v.y = fmaxf(fmaf(v.y, sc, sh), 0.f);
    v.z = fmaxf(fmaf(v.z, sc, sh), 0.f);
    v.w = fmaxf(fmaf(v.w, sc, sh), 0.f);
    *(float4*)&out[base] = v;
}

// ---------------- launch ----------------
extern "C" void kernel_launch(void* const* d_in, const int* in_sizes, int n_in,
                              void* d_out, int out_size) {
    const float* x     = (const float*)d_in[0];
    const float* w_off = (const float*)d_in[1];
    const float* b_off = (const float*)d_in[2];
    const float* gno_w = (const float*)d_in[3];
    const float* gno_b = (const float*)d_in[4];
    const float* w_dsc = (const float*)d_in[5];
    const float* b_dsc = (const float*)d_in[6];
    const float* gn_w  = (const float*)d_in[7];
    const float* gn_b  = (const float*)d_in[8];
    float* out = (float*)d_out;

    cudaFuncSetAttribute(main_kernel, cudaFuncAttributeMaxDynamicSharedMemorySize, SMEM_BYTES);

    conv1_kernel<<<dim3(WW/32, HH/8, BN), 256>>>(x, w_off, b_off);
    offstats_kernel<<<BN*5, 256>>>();
    wprep_kernel<<<(KK*64*64 + 255)/256, 256>>>(w_dsc);
    main_kernel<<<dim3(2, HH, BN), 256, SMEM_BYTES>>>(x, gno_w, gno_b, b_dsc, out);
    outstats_kernel<<<BN*16, 256>>>();
    apply_kernel<<<4096, 512>>>(out, gn_w, gn_b);
}